// round 6
// baseline (speedup 1.0000x reference)
#include <cuda_runtime.h>

// Problem constants (fixed by setup_inputs)
#define NB 4
#define CC 128
#define HH 160
#define WW 320
#define DD 48

#define WT   128          // w-tile per CTA
#define RT   (WT + 48)    // right tile width incl. disparity halo = 176
#define CHS  64           // channels staged per pass
#define NTHR 128          // 4 warps: one per SMSP, each owns 12 disparities

// smem: L[CHS][WT] + R[CHS][RT] = 64*128 + 64*176 floats = 19456 floats = 77824 B
#define SMEM_FLOATS (CHS*WT + CHS*RT)

__global__ __launch_bounds__(NTHR, 2)
void cost_volume_kernel(const float* __restrict__ left,
                        const float* __restrict__ right,
                        float* __restrict__ out)
{
    extern __shared__ float smem[];
    float* Ls = smem;              // [CHS][WT]
    float* Rs = smem + CHS * WT;   // [CHS][RT]

    const int tid  = threadIdx.x;
    const int lane = tid & 31;
    const int warp = tid >> 5;          // 0..3
    const int w0   = blockIdx.x * WT;   // 0,128,256 (last tile partial)
    const int h    = blockIdx.y;
    const int n    = blockIdx.z;
    const int d0   = warp * 12;         // disparity group base

    // R smem window base for this thread: global w of Rs[i] is (w0-48+i).
    // acc[dj][wi] needs R at w0+4*lane+wi-(d0+dj) -> Rs index 4*lane-d0+48+wi-dj,
    // wi-dj in [-11,3]. Aligned window start:
    const int ib = 4 * lane - d0 + 36;  // multiple of 4; in [0,160]

    float acc[12][4];
    #pragma unroll
    for (int j = 0; j < 12; j++)
        #pragma unroll
        for (int i = 0; i < 4; i++) acc[j][i] = 0.0f;

    const size_t chan_stride = (size_t)HH * WW;

    for (int c0 = 0; c0 < CC; c0 += CHS) {
        // ---- stage left tile: CHS rows of 128 floats (float4, zero beyond W) ----
        {
            const float* lbase = left + ((size_t)(n * CC + c0) * HH + h) * WW;
            #pragma unroll 4
            for (int idx = tid; idx < CHS * (WT / 4); idx += NTHR) {
                int c  = idx / (WT / 4);
                int wq = (idx - c * (WT / 4)) * 4;
                int gw = w0 + wq;                    // multiple of 4; WW mult of 4
                float4 v = make_float4(0.f, 0.f, 0.f, 0.f);
                if (gw < WW) v = *(const float4*)(lbase + c * chan_stride + gw);
                *(float4*)(Ls + c * WT + wq) = v;
            }
        }
        // ---- stage right tile: CHS rows of 176 floats, halo zero-filled ----
        {
            const float* rbase = right + ((size_t)(n * CC + c0) * HH + h) * WW;
            #pragma unroll 4
            for (int idx = tid; idx < CHS * (RT / 4); idx += NTHR) {
                int c  = idx / (RT / 4);
                int wq = (idx - c * (RT / 4)) * 4;
                int gw = w0 - 48 + wq;               // multiple of 4
                float4 v = make_float4(0.f, 0.f, 0.f, 0.f);
                if (gw >= 0 && gw < WW) v = *(const float4*)(rbase + c * chan_stride + gw);
                *(float4*)(Rs + c * RT + wq) = v;
            }
        }
        __syncthreads();

        // ---- FFMA mainloop: per channel 5 LDS.128 -> 48 FMAs ----
        const float* lp = Ls + 4 * lane;
        const float* rp = Rs + ib;
        #pragma unroll 2
        for (int c = 0; c < CHS; c++) {
            float4 lv = *(const float4*)(lp + c * WT);
            float lw[4] = { lv.x, lv.y, lv.z, lv.w };
            float r[16];
            #pragma unroll
            for (int k = 0; k < 4; k++) {
                float4 rv = *(const float4*)(rp + c * RT + 4 * k);
                r[4*k+0] = rv.x; r[4*k+1] = rv.y; r[4*k+2] = rv.z; r[4*k+3] = rv.w;
            }
            #pragma unroll
            for (int dj = 0; dj < 12; dj++)
                #pragma unroll
                for (int wi = 0; wi < 4; wi++)
                    acc[dj][wi] = fmaf(lw[wi], r[wi - dj + 12], acc[dj][wi]);
        }
        __syncthreads();   // buffer reused next pass
    }

    // ---- store: float4 per disparity row; last tile guarded (gw mult of 4) ----
    const int gw = w0 + 4 * lane;
    if (gw < WW) {
        #pragma unroll
        for (int dj = 0; dj < 12; dj++) {
            int d = d0 + dj;
            float4 v = make_float4(acc[dj][0], acc[dj][1], acc[dj][2], acc[dj][3]);
            *(float4*)(out + (((size_t)(n * DD + d) * HH + h) * WW + gw)) = v;
        }
    }
}

extern "C" void kernel_launch(void* const* d_in, const int* in_sizes, int n_in,
                              void* d_out, int out_size)
{
    const float* left  = (const float*)d_in[0];
    const float* right = (const float*)d_in[1];
    float* out = (float*)d_out;

    cudaFuncSetAttribute(cost_volume_kernel,
                         cudaFuncAttributeMaxDynamicSharedMemorySize,
                         SMEM_FLOATS * (int)sizeof(float));

    dim3 grid((WW + WT - 1) / WT, HH, NB);   // (3, 160, 4)
    cost_volume_kernel<<<grid, NTHR, SMEM_FLOATS * sizeof(float)>>>(left, right, out);
}

// round 7
// speedup vs baseline: 2.0418x; 2.0418x over previous
#include <cuda_runtime.h>
#include <cstdint>

// Problem constants (fixed by setup_inputs)
#define NB 4
#define CC 128
#define HH 160
#define WW 320
#define DD 48

#define WT   128            // w-tile per CTA
#define RT   (WT + 48)      // right tile width incl. disparity halo = 176
#define CHS  16             // channels per pipeline stage
#define NSTG (CC / CHS)     // 8 stages
#define NTHR 128            // 4 warps: one per SMSP, each owns 12 disparities

#define STAGE_FLOATS (CHS * (WT + RT))     // 4864 floats = 19456 B
#define SMEM_FLOATS  (2 * STAGE_FLOATS)    // double buffer: 38912 B

__device__ __forceinline__ uint32_t smem_u32(const void* p) {
    return (uint32_t)__cvta_generic_to_shared(p);
}
// 16B async copy, global->shared, with zero-fill when bytes==0 (halo padding).
__device__ __forceinline__ void cp16(uint32_t dst, const void* src, int bytes) {
    asm volatile("cp.async.cg.shared.global [%0], [%1], 16, %2;"
                 :: "r"(dst), "l"(src), "r"(bytes));
}

__global__ void __launch_bounds__(NTHR, 4)
cost_volume_kernel(const float* __restrict__ left,
                   const float* __restrict__ right,
                   float* __restrict__ out)
{
    __shared__ float smem[SMEM_FLOATS];

    const int tid  = threadIdx.x;
    const int lane = tid & 31;
    const int warp = tid >> 5;          // 0..3
    const int w0   = blockIdx.x * WT;   // 0,128,256 (last tile partial)
    const int h    = blockIdx.y;
    const int n    = blockIdx.z;
    const int d0   = warp * 12;         // disparity group base

    // acc[dj][wi] needs R at smem window index 4*lane - d0 + 36 + (wi - dj + 12),
    // wi-dj+12 in [1,15]. Window start is a multiple of 4 -> pure float4 LDS.
    const int ib = 4 * lane - d0 + 36;

    const size_t chan_stride = (size_t)HH * WW;
    const float* lrow = left  + (size_t)n * CC * chan_stride + (size_t)h * WW;
    const float* rrow = right + (size_t)n * CC * chan_stride + (size_t)h * WW;

    // ---- async prefetch of one CHS-channel stage into buffer `buf` ----
    auto prefetch = [&](int c0, float* buf) {
        float* Ls = buf;                 // [CHS][WT]
        float* Rs = buf + CHS * WT;      // [CHS][RT]
        const float* lb = lrow + (size_t)c0 * chan_stride;
        const float* rb = rrow + (size_t)c0 * chan_stride;
        // L: CHS*WT/4 = 512 float4, 4 per thread
        #pragma unroll
        for (int it = 0; it < 4; it++) {
            int idx = tid + it * NTHR;       // 0..511
            int c   = idx >> 5;              // /(WT/4)
            int wq  = (idx & 31) << 2;
            int gw  = w0 + wq;
            bool ok = (gw < WW);
            const float* src = ok ? (lb + (size_t)c * chan_stride + gw) : lb;
            cp16(smem_u32(Ls + c * WT + wq), src, ok ? 16 : 0);
        }
        // R: CHS*RT/4 = 704 float4
        #pragma unroll
        for (int it = 0; it < 6; it++) {
            int idx = tid + it * NTHR;
            if (idx < CHS * (RT / 4)) {
                int c  = idx / (RT / 4);
                int wq = (idx - c * (RT / 4)) << 2;
                int gw = w0 - 48 + wq;
                bool ok = (gw >= 0) && (gw < WW);
                const float* src = ok ? (rb + (size_t)c * chan_stride + gw) : rb;
                cp16(smem_u32(Rs + c * RT + wq), src, ok ? 16 : 0);
            }
        }
        asm volatile("cp.async.commit_group;");
    };

    float acc[12][4];
    #pragma unroll
    for (int j = 0; j < 12; j++)
        #pragma unroll
        for (int i = 0; i < 4; i++) acc[j][i] = 0.0f;

    prefetch(0, smem);

    for (int s = 0; s < NSTG; s++) {
        float* cur = smem + (s & 1) * STAGE_FLOATS;
        if (s + 1 < NSTG) {
            // buffer (s+1)&1 held stage s-1; trailing barrier of iter s-1 protects it
            prefetch((s + 1) * CHS, smem + ((s + 1) & 1) * STAGE_FLOATS);
            asm volatile("cp.async.wait_group 1;");   // stage s complete
        } else {
            asm volatile("cp.async.wait_group 0;");
        }
        __syncthreads();   // stage-s data visible to all warps

        // ---- FFMA mainloop: per channel 5 LDS.128 -> 48 FMAs ----
        const float* lp = cur + 4 * lane;
        const float* rp = cur + CHS * WT + ib;
        #pragma unroll
        for (int c = 0; c < CHS; c++) {
            float4 lv = *(const float4*)(lp + c * WT);
            float lw[4] = { lv.x, lv.y, lv.z, lv.w };
            float r[16];
            #pragma unroll
            for (int k = 0; k < 4; k++) {
                float4 rv = *(const float4*)(rp + c * RT + 4 * k);
                r[4*k+0] = rv.x; r[4*k+1] = rv.y; r[4*k+2] = rv.z; r[4*k+3] = rv.w;
            }
            #pragma unroll
            for (int dj = 0; dj < 12; dj++)
                #pragma unroll
                for (int wi = 0; wi < 4; wi++)
                    acc[dj][wi] = fmaf(lw[wi], r[wi - dj + 12], acc[dj][wi]);
        }
        __syncthreads();   // compute done before next prefetch overwrites this buffer
    }

    // ---- store: float4 per disparity row; last tile guarded ----
    const int gw = w0 + 4 * lane;
    if (gw < WW) {
        #pragma unroll
        for (int dj = 0; dj < 12; dj++) {
            int d = d0 + dj;
            float4 v = make_float4(acc[dj][0], acc[dj][1], acc[dj][2], acc[dj][3]);
            *(float4*)(out + (((size_t)(n * DD + d) * HH + h) * WW + gw)) = v;
        }
    }
}

extern "C" void kernel_launch(void* const* d_in, const int* in_sizes, int n_in,
                              void* d_out, int out_size)
{
    const float* left  = (const float*)d_in[0];
    const float* right = (const float*)d_in[1];
    float* out = (float*)d_out;

    dim3 grid((WW + WT - 1) / WT, HH, NB);   // (3, 160, 4)
    cost_volume_kernel<<<grid, NTHR>>>(left, right, out);
}